// round 5
// baseline (speedup 1.0000x reference)
#include <cuda_runtime.h>
#include <cstdint>

#define BB 16
#define DD 256
#define TT 2048
#define KK 8192
#define NN (BB*TT)          /* 32768 tokens  */
#define NQ (BB*DD*TT)       /* 8388608 elems */

typedef unsigned long long ull;

// Scratch (static __device__ arrays: allocation-free per harness rules)
__device__ float g_embT[DD*KK];    // emb transposed [D][K], 8 MB
__device__ float g_enorm[KK];      // ||e_k||^2
__device__ int   g_idx[NN];        // argmin per token
__device__ float g_partial[1024];  // loss partials

// packed f32x2 helpers: two INDEPENDENT fp32 FMAs per instruction (bit-exact
// vs scalar FFMA, same per-lane rounding) — ptxas only emits FFMA2 via PTX.
__device__ __forceinline__ void ffma2(ull &d, ull a, ull b) {
    asm("fma.rn.f32x2 %0, %1, %2, %0;" : "+l"(d) : "l"(a), "l"(b));
}
__device__ __forceinline__ ull bcast2(float x) {
    ull r;
    asm("mov.b64 %0, {%1, %1};" : "=l"(r) : "f"(x));
    return r;
}

// ---------------------------------------------------------------------------
// emb [K,D] -> embT [D,K]
__global__ void k_transpose(const float* __restrict__ emb) {
    __shared__ float tile[32][33];
    int k0 = blockIdx.x * 32, d0 = blockIdx.y * 32;
    int tx = threadIdx.x, ty = threadIdx.y;
    #pragma unroll
    for (int i = 0; i < 32; i += 8)
        tile[ty + i][tx] = emb[(size_t)(k0 + ty + i) * DD + d0 + tx];
    __syncthreads();
    #pragma unroll
    for (int i = 0; i < 32; i += 8)
        g_embT[(size_t)(d0 + ty + i) * KK + k0 + tx] = tile[tx][ty + i];
}

// per-code squared norms (deterministic order)
__global__ void k_norms(const float* __restrict__ emb) {
    int r = blockIdx.x * 8 + (threadIdx.x >> 5);
    int lane = threadIdx.x & 31;
    float s = 0.f;
    for (int i = lane; i < DD; i += 32) {
        float v = emb[(size_t)r * DD + i];
        s += v * v;
    }
    #pragma unroll
    for (int o = 16; o > 0; o >>= 1) s += __shfl_xor_sync(0xffffffffu, s, o);
    if (lane == 0) g_enorm[r] = s;
}

// ---------------------------------------------------------------------------
// Fused distance + argmin: 128 tokens x 128 codes per block tile, FFMA2 core.
__global__ __launch_bounds__(256, 2)
void k_argmin(const float* __restrict__ z, float* __restrict__ idxOutF, int writeIdx) {
    __shared__ float As[8][128];
    __shared__ float Bs[8][128];
    __shared__ float s1s[128];
    __shared__ float ens[128];
    __shared__ float rbd[128][16];
    __shared__ int   rbi[128][16];

    int tid = threadIdx.x;
    int ty = tid >> 4, tx = tid & 15;
    int ntile = blockIdx.x;            // 256 tiles of 128 tokens
    int bimg = ntile >> 4;
    int t0 = (ntile & 15) * 128;
    const float* zb = z + (size_t)bimg * DD * TT;

    float bd[8]; int bi[8];
    #pragma unroll
    for (int i = 0; i < 8; i++) { bd[i] = 3.4e38f; bi[i] = 0x7fffffff; }
    float s1acc[8];
    #pragma unroll
    for (int i = 0; i < 8; i++) s1acc[i] = 0.f;

    // one float4 of As and one of Bs per thread per d-chunk
    int ldd = tid >> 5;                 // 0..7
    int lc4 = (tid & 31) << 2;          // 0..124

    for (int ct = 0; ct < KK / 128; ct++) {
        int k0 = ct * 128;
        ull acc2[8][4];                 // [i][j2], lanes = codes 2*j2, 2*j2+1
        #pragma unroll
        for (int i = 0; i < 8; i++)
            #pragma unroll
            for (int j = 0; j < 4; j++) acc2[i][j] = 0ull;

        if (tid < 128) ens[tid] = g_enorm[k0 + tid];

        // prefetch dc=0 into registers
        float4 pa = *(const float4*)&zb[(size_t)ldd * TT + t0 + lc4];
        float4 pb = *(const float4*)&g_embT[(size_t)ldd * KK + k0 + lc4];

        for (int dc = 0; dc < DD / 8; dc++) {
            __syncthreads();           // prior compute done (and epilogue's ens reads)
            *(float4*)&As[ldd][lc4] = pa;
            *(float4*)&Bs[ldd][lc4] = pb;
            __syncthreads();           // tile visible
            if (dc < DD / 8 - 1) {     // issue next loads; latency overlaps compute
                int d0 = (dc + 1) * 8;
                pa = *(const float4*)&zb[(size_t)(d0 + ldd) * TT + t0 + lc4];
                pb = *(const float4*)&g_embT[(size_t)(d0 + ldd) * KK + k0 + lc4];
            }
            #pragma unroll
            for (int kk = 0; kk < 8; kk++) {
                float a[8];
                *(float4*)(a)     = *(float4*)&As[kk][ty * 8];
                *(float4*)(a + 4) = *(float4*)&As[kk][ty * 8 + 4];
                ulonglong2 q0 = *(ulonglong2*)&Bs[kk][tx * 8];
                ulonglong2 q1 = *(ulonglong2*)&Bs[kk][tx * 8 + 4];
                ull b2[4] = { q0.x, q0.y, q1.x, q1.y };
                ull a2[8];
                #pragma unroll
                for (int i = 0; i < 8; i++) a2[i] = bcast2(a[i]);
                #pragma unroll
                for (int i = 0; i < 8; i++)
                    #pragma unroll
                    for (int j = 0; j < 4; j++)
                        ffma2(acc2[i][j], a2[i], b2[j]);
                if (ct == 0 && tx == 0) {      // row norms, once
                    #pragma unroll
                    for (int i = 0; i < 8; i++) s1acc[i] += a[i] * a[i];
                }
            }
        }
        if (ct == 0 && tx == 0) {
            #pragma unroll
            for (int i = 0; i < 8; i++) s1s[ty * 8 + i] = s1acc[i];
        }
        __syncthreads();   // s1s + ens visible, compute done

        // epilogue: distance (reference rounding order) + running argmin
        #pragma unroll
        for (int i = 0; i < 8; i++) {
            float s1 = s1s[ty * 8 + i];
            #pragma unroll
            for (int j2 = 0; j2 < 4; j2++) {
                float2 v = *(float2*)&acc2[i][j2];
                float c0 = s1 + ens[tx * 8 + j2 * 2];
                float d0 = c0 - 2.0f * v.x;
                if (d0 < bd[i]) { bd[i] = d0; bi[i] = k0 + tx * 8 + j2 * 2; }
                float c1 = s1 + ens[tx * 8 + j2 * 2 + 1];
                float d1 = c1 - 2.0f * v.y;
                if (d1 < bd[i]) { bd[i] = d1; bi[i] = k0 + tx * 8 + j2 * 2 + 1; }
            }
        }
        __syncthreads();   // before next ct rewrites ens
    }

    // cross-tx reduction with first-index tie-break
    #pragma unroll
    for (int i = 0; i < 8; i++) { rbd[ty * 8 + i][tx] = bd[i]; rbi[ty * 8 + i][tx] = bi[i]; }
    __syncthreads();
    if (tid < 128) {
        float best = rbd[tid][0]; int besti = rbi[tid][0];
        #pragma unroll
        for (int x = 1; x < 16; x++) {
            float d = rbd[tid][x]; int ii = rbi[tid][x];
            if (d < best || (d == best && ii < besti)) { best = d; besti = ii; }
        }
        int n = ntile * 128 + tid;
        g_idx[n] = besti;
        if (writeIdx) idxOutF[n] = (float)besti;
    }
}

// ---------------------------------------------------------------------------
// Gather + straight-through output + loss partials (deterministic order)
__global__ void k_quant(const float* __restrict__ z, float* __restrict__ out) {
    __shared__ float red[256];
    size_t base = (size_t)blockIdx.x * 8192;
    float ls = 0.f;
    #pragma unroll 4
    for (int j = 0; j < 32; j++) {
        size_t i = base + threadIdx.x + (size_t)j * 256;
        int t = (int)(i & (TT - 1));
        int d = (int)((i >> 11) & (DD - 1));
        int b = (int)(i >> 19);
        int n = b * TT + t;
        float zv = z[i];
        float q  = g_embT[(size_t)d * KK + g_idx[n]];
        float diff = q - zv;
        out[i] = zv + diff;                // z + (q - z): reference rounding
        ls += diff * diff;
    }
    red[threadIdx.x] = ls;
    __syncthreads();
    #pragma unroll
    for (int o = 128; o > 0; o >>= 1) {
        if (threadIdx.x < o) red[threadIdx.x] += red[threadIdx.x + o];
        __syncthreads();
    }
    if (threadIdx.x == 0) g_partial[blockIdx.x] = red[0];
}

__global__ void k_final(float* out_loss, int doWrite) {
    __shared__ float red[256];
    float s = 0.f;
    #pragma unroll
    for (int j = 0; j < 4; j++) s += g_partial[threadIdx.x + j * 256];
    red[threadIdx.x] = s;
    __syncthreads();
    #pragma unroll
    for (int o = 128; o > 0; o >>= 1) {
        if (threadIdx.x < o) red[threadIdx.x] += red[threadIdx.x + o];
        __syncthreads();
    }
    if (threadIdx.x == 0 && doWrite)
        out_loss[0] = 1.25f * (red[0] / (float)NQ);
}

// ---------------------------------------------------------------------------
extern "C" void kernel_launch(void* const* d_in, const int* in_sizes, int n_in,
                              void* d_out, int out_size) {
    const float* z   = (const float*)d_in[0];
    const float* emb = (const float*)d_in[1];
    if (n_in >= 2 && in_sizes[0] == KK * DD && in_sizes[1] == NQ) {
        const float* tmp = z; z = emb; emb = tmp;   // defensive input-order swap
    }
    float* out = (float*)d_out;
    int writeTail = (out_size >= NQ + 1 + NN) ? 1 : 0;

    k_transpose<<<dim3(KK / 32, DD / 32), dim3(32, 8)>>>(emb);
    k_norms<<<KK / 8, 256>>>(emb);
    k_argmin<<<NN / 128, 256>>>(z, out + NQ + 1, writeTail);
    k_quant<<<1024, 256>>>(z, out);
    k_final<<<1, 256>>>(out + NQ, writeTail);
}

// round 6
// speedup vs baseline: 1.0019x; 1.0019x over previous
#include <cuda_runtime.h>
#include <cstdint>

#define BB 16
#define DD 256
#define TT 2048
#define KK 8192
#define NN (BB*TT)          /* 32768 tokens  */
#define NQ (BB*DD*TT)       /* 8388608 elems */

typedef unsigned long long ull;

// Scratch (static __device__ arrays: allocation-free per harness rules)
__device__ float g_embT[DD*KK];    // emb transposed [D][K], 8 MB
__device__ float g_enorm[KK];      // ||e_k||^2
__device__ int   g_idx[NN];        // argmin per token
__device__ float g_partial[1024];  // loss partials

// packed f32x2 helpers: two INDEPENDENT fp32 FMAs per instruction (bit-exact
// vs scalar FFMA, same per-lane rounding) — ptxas only emits FFMA2 via PTX.
__device__ __forceinline__ void ffma2(ull &d, ull a, ull b) {
    asm("fma.rn.f32x2 %0, %1, %2, %0;" : "+l"(d) : "l"(a), "l"(b));
}
__device__ __forceinline__ ull bcast2(float x) {
    ull r;
    asm("mov.b64 %0, {%1, %1};" : "=l"(r) : "f"(x));
    return r;
}

// ---------------------------------------------------------------------------
// emb [K,D] -> embT [D,K]
__global__ void k_transpose(const float* __restrict__ emb) {
    __shared__ float tile[32][33];
    int k0 = blockIdx.x * 32, d0 = blockIdx.y * 32;
    int tx = threadIdx.x, ty = threadIdx.y;
    #pragma unroll
    for (int i = 0; i < 32; i += 8)
        tile[ty + i][tx] = emb[(size_t)(k0 + ty + i) * DD + d0 + tx];
    __syncthreads();
    #pragma unroll
    for (int i = 0; i < 32; i += 8)
        g_embT[(size_t)(d0 + ty + i) * KK + k0 + tx] = tile[tx][ty + i];
}

// per-code squared norms (deterministic order)
__global__ void k_norms(const float* __restrict__ emb) {
    int r = blockIdx.x * 8 + (threadIdx.x >> 5);
    int lane = threadIdx.x & 31;
    float s = 0.f;
    for (int i = lane; i < DD; i += 32) {
        float v = emb[(size_t)r * DD + i];
        s += v * v;
    }
    #pragma unroll
    for (int o = 16; o > 0; o >>= 1) s += __shfl_xor_sync(0xffffffffu, s, o);
    if (lane == 0) g_enorm[r] = s;
}

// ---------------------------------------------------------------------------
// Fused distance + argmin: 128 tokens x 128 codes per block tile, FFMA2 core.
__global__ __launch_bounds__(256, 2)
void k_argmin(const float* __restrict__ z, float* __restrict__ idxOutF, int writeIdx) {
    __shared__ float As[8][128];
    __shared__ float Bs[8][128];
    __shared__ float s1s[128];
    __shared__ float ens[128];
    __shared__ float rbd[128][16];
    __shared__ int   rbi[128][16];

    int tid = threadIdx.x;
    int ty = tid >> 4, tx = tid & 15;
    int ntile = blockIdx.x;            // 256 tiles of 128 tokens
    int bimg = ntile >> 4;
    int t0 = (ntile & 15) * 128;
    const float* zb = z + (size_t)bimg * DD * TT;

    float bd[8]; int bi[8];
    #pragma unroll
    for (int i = 0; i < 8; i++) { bd[i] = 3.4e38f; bi[i] = 0x7fffffff; }
    float s1acc[8];
    #pragma unroll
    for (int i = 0; i < 8; i++) s1acc[i] = 0.f;

    // one float4 of As and one of Bs per thread per d-chunk
    int ldd = tid >> 5;                 // 0..7
    int lc4 = (tid & 31) << 2;          // 0..124

    for (int ct = 0; ct < KK / 128; ct++) {
        int k0 = ct * 128;
        ull acc2[8][4];                 // [i][j2], lanes = codes 2*j2, 2*j2+1
        #pragma unroll
        for (int i = 0; i < 8; i++)
            #pragma unroll
            for (int j = 0; j < 4; j++) acc2[i][j] = 0ull;

        if (tid < 128) ens[tid] = g_enorm[k0 + tid];

        // prefetch dc=0 into registers
        float4 pa = *(const float4*)&zb[(size_t)ldd * TT + t0 + lc4];
        float4 pb = *(const float4*)&g_embT[(size_t)ldd * KK + k0 + lc4];

        for (int dc = 0; dc < DD / 8; dc++) {
            __syncthreads();           // prior compute done (and epilogue's ens reads)
            *(float4*)&As[ldd][lc4] = pa;
            *(float4*)&Bs[ldd][lc4] = pb;
            __syncthreads();           // tile visible
            if (dc < DD / 8 - 1) {     // issue next loads; latency overlaps compute
                int d0 = (dc + 1) * 8;
                pa = *(const float4*)&zb[(size_t)(d0 + ldd) * TT + t0 + lc4];
                pb = *(const float4*)&g_embT[(size_t)(d0 + ldd) * KK + k0 + lc4];
            }
            #pragma unroll
            for (int kk = 0; kk < 8; kk++) {
                float a[8];
                *(float4*)(a)     = *(float4*)&As[kk][ty * 8];
                *(float4*)(a + 4) = *(float4*)&As[kk][ty * 8 + 4];
                ulonglong2 q0 = *(ulonglong2*)&Bs[kk][tx * 8];
                ulonglong2 q1 = *(ulonglong2*)&Bs[kk][tx * 8 + 4];
                ull b2[4] = { q0.x, q0.y, q1.x, q1.y };
                ull a2[8];
                #pragma unroll
                for (int i = 0; i < 8; i++) a2[i] = bcast2(a[i]);
                #pragma unroll
                for (int i = 0; i < 8; i++)
                    #pragma unroll
                    for (int j = 0; j < 4; j++)
                        ffma2(acc2[i][j], a2[i], b2[j]);
                if (ct == 0 && tx == 0) {      // row norms, once
                    #pragma unroll
                    for (int i = 0; i < 8; i++) s1acc[i] += a[i] * a[i];
                }
            }
        }
        if (ct == 0 && tx == 0) {
            #pragma unroll
            for (int i = 0; i < 8; i++) s1s[ty * 8 + i] = s1acc[i];
        }
        __syncthreads();   // s1s + ens visible, compute done

        // epilogue: distance (reference rounding order) + running argmin
        #pragma unroll
        for (int i = 0; i < 8; i++) {
            float s1 = s1s[ty * 8 + i];
            #pragma unroll
            for (int j2 = 0; j2 < 4; j2++) {
                float2 v = *(float2*)&acc2[i][j2];
                float c0 = s1 + ens[tx * 8 + j2 * 2];
                float d0 = c0 - 2.0f * v.x;
                if (d0 < bd[i]) { bd[i] = d0; bi[i] = k0 + tx * 8 + j2 * 2; }
                float c1 = s1 + ens[tx * 8 + j2 * 2 + 1];
                float d1 = c1 - 2.0f * v.y;
                if (d1 < bd[i]) { bd[i] = d1; bi[i] = k0 + tx * 8 + j2 * 2 + 1; }
            }
        }
        __syncthreads();   // before next ct rewrites ens
    }

    // cross-tx reduction with first-index tie-break
    #pragma unroll
    for (int i = 0; i < 8; i++) { rbd[ty * 8 + i][tx] = bd[i]; rbi[ty * 8 + i][tx] = bi[i]; }
    __syncthreads();
    if (tid < 128) {
        float best = rbd[tid][0]; int besti = rbi[tid][0];
        #pragma unroll
        for (int x = 1; x < 16; x++) {
            float d = rbd[tid][x]; int ii = rbi[tid][x];
            if (d < best || (d == best && ii < besti)) { best = d; besti = ii; }
        }
        int n = ntile * 128 + tid;
        g_idx[n] = besti;
        if (writeIdx) idxOutF[n] = (float)besti;
    }
}

// ---------------------------------------------------------------------------
// Gather + straight-through output + loss partials (deterministic order)
__global__ void k_quant(const float* __restrict__ z, float* __restrict__ out) {
    __shared__ float red[256];
    size_t base = (size_t)blockIdx.x * 8192;
    float ls = 0.f;
    #pragma unroll 4
    for (int j = 0; j < 32; j++) {
        size_t i = base + threadIdx.x + (size_t)j * 256;
        int t = (int)(i & (TT - 1));
        int d = (int)((i >> 11) & (DD - 1));
        int b = (int)(i >> 19);
        int n = b * TT + t;
        float zv = z[i];
        float q  = g_embT[(size_t)d * KK + g_idx[n]];
        float diff = q - zv;
        out[i] = zv + diff;                // z + (q - z): reference rounding
        ls += diff * diff;
    }
    red[threadIdx.x] = ls;
    __syncthreads();
    #pragma unroll
    for (int o = 128; o > 0; o >>= 1) {
        if (threadIdx.x < o) red[threadIdx.x] += red[threadIdx.x + o];
        __syncthreads();
    }
    if (threadIdx.x == 0) g_partial[blockIdx.x] = red[0];
}

__global__ void k_final(float* out_loss, int doWrite) {
    __shared__ float red[256];
    float s = 0.f;
    #pragma unroll
    for (int j = 0; j < 4; j++) s += g_partial[threadIdx.x + j * 256];
    red[threadIdx.x] = s;
    __syncthreads();
    #pragma unroll
    for (int o = 128; o > 0; o >>= 1) {
        if (threadIdx.x < o) red[threadIdx.x] += red[threadIdx.x + o];
        __syncthreads();
    }
    if (threadIdx.x == 0 && doWrite)
        out_loss[0] = 1.25f * (red[0] / (float)NQ);
}

// ---------------------------------------------------------------------------
extern "C" void kernel_launch(void* const* d_in, const int* in_sizes, int n_in,
                              void* d_out, int out_size) {
    const float* z   = (const float*)d_in[0];
    const float* emb = (const float*)d_in[1];
    if (n_in >= 2 && in_sizes[0] == KK * DD && in_sizes[1] == NQ) {
        const float* tmp = z; z = emb; emb = tmp;   // defensive input-order swap
    }
    float* out = (float*)d_out;
    int writeTail = (out_size >= NQ + 1 + NN) ? 1 : 0;

    k_transpose<<<dim3(KK / 32, DD / 32), dim3(32, 8)>>>(emb);
    k_norms<<<KK / 8, 256>>>(emb);
    k_argmin<<<NN / 128, 256>>>(z, out + NQ + 1, writeTail);
    k_quant<<<1024, 256>>>(z, out);
    k_final<<<1, 256>>>(out + NQ, writeTail);
}